// round 1
// baseline (speedup 1.0000x reference)
#include <cuda_runtime.h>
#include <cuda_bf16.h>

// Wav2Frames: out[b, c, f] = x[b, f*WINSTEP + c]
// (conv1d with identity eye(WINLEN) kernel, stride WINSTEP, VALID padding)
//
// Fixed shapes from the reference:
//   x: (32, 1, 480000) fp32, W: eye(400), winstep = 160
//   out: (32, 400, 2998) fp32
//
// Strategy: per-CTA smem staging. CTA = (frame tile of 32, batch b).
//  - coalesced load of the contiguous input span (5360 floats) into smem
//    with a skew layout phys(i) = i + (i>>5)  (conflict-free on both sides)
//  - coalesced writes: each warp writes 32 consecutive f's of one output row c.

#define B       32
#define T       480000
#define WINLEN  400
#define WINSTEP 160
#define NFRAMES 2998              // floor((T - WINLEN)/WINSTEP) + 1
#define F_TILE  32
#define NTILES  ((NFRAMES + F_TILE - 1) / F_TILE)   // 94
#define SPAN    ((F_TILE - 1) * WINSTEP + WINLEN)   // 5360 floats
#define SM_PAD  (SPAN + SPAN / 32 + 1)              // skewed size

__global__ __launch_bounds__(256)
void wav2frames_kernel(const float* __restrict__ x, float* __restrict__ out) {
    __shared__ float sm[SM_PAD];

    const int tile = blockIdx.x;          // frame tile
    const int b    = blockIdx.y;          // batch
    const int tid  = threadIdx.x;

    const int f0 = tile * F_TILE;
    const int x0 = f0 * WINSTEP;

    // ---- coalesced load of the input span into skewed smem ----
    const float* __restrict__ xb = x + (size_t)b * T + x0;
    const int span = (x0 + SPAN <= T) ? SPAN : (T - x0);

    for (int i = tid; i < span; i += 256) {
        sm[i + (i >> 5)] = xb[i];
    }
    __syncthreads();

    // ---- coalesced writes: lane = f within tile, warp row-steps over c ----
    const int fl = tid & 31;              // frame-local index (lane)
    const int cg = tid >> 5;              // warp id -> c starting offset
    const int f  = f0 + fl;

    if (f < NFRAMES) {
        float* __restrict__ ob = out + (size_t)b * WINLEN * NFRAMES + f;
        const int jbase = fl * WINSTEP;
        #pragma unroll 10
        for (int c = cg; c < WINLEN; c += 8) {
            const int j = jbase + c;
            ob[(size_t)c * NFRAMES] = sm[j + (j >> 5)];
        }
    }
}

extern "C" void kernel_launch(void* const* d_in, const int* in_sizes, int n_in,
                              void* d_out, int out_size) {
    const float* x = (const float*)d_in[0];     // (32, 1, 480000) fp32
    // d_in[1] = W (identity, unused), d_in[2] = winstep (fixed 160, unused)
    float* out = (float*)d_out;                 // (32, 400, 2998) fp32

    dim3 grid(NTILES, B);   // 94 x 32 = 3008 CTAs
    wav2frames_kernel<<<grid, 256>>>(x, out);
}

// round 2
// speedup vs baseline: 1.2892x; 1.2892x over previous
#include <cuda_runtime.h>
#include <cuda_bf16.h>

// Wav2Frames: out[b, c, f] = x[b, f*WINSTEP + c]
// (conv1d with identity eye(400) kernel, stride 160, VALID padding)
//
// x: (32, 1, 480000) fp32 -> out: (32, 400, 2998) fp32
//
// R2 changes vs R1:
//  - F_TILE 32 -> 64 (half the CTAs, half the read overlap, fewer syncs)
//  - fill loop vectorized to float4 LDG
//  - store loop vectorized to float2 STG (lane owns a frame PAIR);
//    smem skew phys = j + (j>>5) leaves only a 2-way LDS conflict,
//    acceptable since L1/shared is far from saturation.
//  - 512 threads/CTA, 25 store iterations/thread, unrolled.

#define B       32
#define T       480000
#define WINLEN  400
#define WINSTEP 160
#define NFRAMES 2998                                  // even
#define F_TILE  64
#define NTILES  ((NFRAMES + F_TILE - 1) / F_TILE)     // 47
#define SPAN    ((F_TILE - 1) * WINSTEP + WINLEN)     // 10480 floats
#define SM_SZ   (SPAN + SPAN / 32 + 4)                // skewed size (~43.2 KB)

__global__ __launch_bounds__(512)
void wav2frames_kernel(const float* __restrict__ x, float* __restrict__ out) {
    __shared__ float sm[SM_SZ];

    const int tile = blockIdx.x;
    const int b    = blockIdx.y;
    const int tid  = threadIdx.x;

    const int f0 = tile * F_TILE;
    const int x0 = f0 * WINSTEP;                      // multiple of 4 -> 16B aligned

    // ---- vectorized coalesced fill: gmem float4 -> skewed smem ----
    const float* __restrict__ xb = x + (size_t)b * T + x0;
    const int span  = (x0 + SPAN <= T) ? SPAN : (T - x0);   // always mult. of 4 here
    const int span4 = span >> 2;
    const float4* __restrict__ xb4 = reinterpret_cast<const float4*>(xb);

    for (int i4 = tid; i4 < span4; i4 += 512) {
        const float4 v = xb4[i4];
        const int i = i4 << 2;                        // i % 4 == 0 -> same 32-block
        const int p = i + (i >> 5);
        sm[p + 0] = v.x;
        sm[p + 1] = v.y;
        sm[p + 2] = v.z;
        sm[p + 3] = v.w;
    }
    __syncthreads();

    // ---- store loop: lane owns frame pair (f, f+1); warp row-steps over c ----
    const int lane = tid & 31;
    const int w    = tid >> 5;                        // 16 warps -> c stride 16
    const int f    = f0 + 2 * lane;

    if (f < NFRAMES) {                                // pairs never split (all even)
        float2* __restrict__ ob =
            reinterpret_cast<float2*>(out + (size_t)b * WINLEN * NFRAMES + f);
        const int jb = 2 * lane * WINSTEP;            // 320 * lane

        #pragma unroll 5
        for (int c = w; c < WINLEN; c += 16) {        // 25 iterations
            const int j0 = jb + c;
            const int j1 = j0 + WINSTEP;
            float2 v;
            v.x = sm[j0 + (j0 >> 5)];
            v.y = sm[j1 + (j1 >> 5)];
            ob[(size_t)c * (NFRAMES / 2)] = v;
        }
    }
}

extern "C" void kernel_launch(void* const* d_in, const int* in_sizes, int n_in,
                              void* d_out, int out_size) {
    const float* x = (const float*)d_in[0];           // (32, 1, 480000) fp32
    // d_in[1] = W (identity, unused), d_in[2] = winstep (fixed 160, unused)
    float* out = (float*)d_out;                       // (32, 400, 2998) fp32

    dim3 grid(NTILES, B);                             // 47 x 32 = 1504 CTAs
    wav2frames_kernel<<<grid, 512>>>(x, out);
}